// round 4
// baseline (speedup 1.0000x reference)
#include <cuda_runtime.h>
#include <cuda_bf16.h>
#include <cstdint>

// Problem constants (fixed shapes)
constexpr int N_NODES = 8192;
constexpr int D = 512;
constexpr int E_EDGES = 131072;
constexpr int B_GR = 16;
constexpr int NPG = 512;
constexpr int S_SEL = 128;
constexpr int L_LAYERS = 3;

// GEMM tiling
constexpr int BM = 128;
constexpr int BN = 128;
constexpr int BK = 32;             // k-chunk
constexpr int NCH = D / BK;        // 16 chunks
constexpr int NMAT = 11;

// smem stage layout (bytes): padded rows of 80B (32 bf16 + 16B pad)
constexpr int ROWB = 80;
constexpr int ZHI = 0;                      // 128*80 = 10240
constexpr int ZLO = 10240;
constexpr int WHI = 20480;                  // 128*80 = 10240
constexpr int WLO = 30720;
constexpr int STAGE = 40960;
constexpr int SM_IDX = 2 * STAGE;           // edge: sDst(512) + sSrc(512)
constexpr int SMEM_GEMM = 2 * STAGE;
constexpr int SMEM_EDGE = 2 * STAGE + 1024;

// -------- static device scratch --------
__device__ float    g_x[N_NODES * D];
__device__ float    g_h[N_NODES * D];
__device__ float    g_A[N_NODES * D];
__device__ float    g_B[N_NODES * D];
__device__ unsigned g_agg[N_NODES * D];
// bf16 weight images: [mat][hi/lo][n][k] row-major (k contiguous)
__device__ __align__(16) __nv_bfloat16 g_Wimg[(size_t)NMAT * 2 * D * D];

// ---------------- helpers ----------------
__device__ __forceinline__ unsigned fenc(float f) {
    unsigned b = __float_as_uint(f);
    return (b & 0x80000000u) ? ~b : (b | 0x80000000u);
}
__device__ __forceinline__ float fdec(unsigned u) {
    unsigned b = (u & 0x80000000u) ? (u & 0x7fffffffu) : ~u;
    return __uint_as_float(b);
}
__device__ __forceinline__ uint32_t smem_u32(const void* p) {
    uint32_t a;
    asm("{ .reg .u64 t; cvta.to.shared.u64 t, %1; cvt.u32.u64 %0, t; }" : "=r"(a) : "l"(p));
    return a;
}
__device__ __forceinline__ void cp16(uint32_t dst, const void* src) {
    asm volatile("cp.async.cg.shared.global [%0], [%1], 16;" :: "r"(dst), "l"(src) : "memory");
}
__device__ __forceinline__ void cp_commit() {
    asm volatile("cp.async.commit_group;" ::: "memory");
}
__device__ __forceinline__ void cp_wait0() {
    asm volatile("cp.async.wait_group 0;" ::: "memory");
}
__device__ __forceinline__ void ldm_x4(uint32_t* r, uint32_t addr) {
    asm volatile("ldmatrix.sync.aligned.m8n8.x4.shared.b16 {%0,%1,%2,%3}, [%4];"
                 : "=r"(r[0]), "=r"(r[1]), "=r"(r[2]), "=r"(r[3]) : "r"(addr));
}
__device__ __forceinline__ void mma16816(float* d, const uint32_t* a, uint32_t b0, uint32_t b1) {
    asm volatile(
        "mma.sync.aligned.m16n8k16.row.col.f32.bf16.bf16.f32 "
        "{%0,%1,%2,%3}, {%4,%5,%6,%7}, {%8,%9}, {%0,%1,%2,%3};"
        : "+f"(d[0]), "+f"(d[1]), "+f"(d[2]), "+f"(d[3])
        : "r"(a[0]), "r"(a[1]), "r"(a[2]), "r"(a[3]), "r"(b0), "r"(b1));
}
// split 2 fp32 -> packed bf16x2 hi + bf16x2 lo
__device__ __forceinline__ void split2(float f0, float f1, uint32_t& hp, uint32_t& lp) {
    uint32_t h;
    asm("cvt.rn.bf16x2.f32 %0, %1, %2;" : "=r"(h) : "f"(f1), "f"(f0));
    float h0 = __uint_as_float(h << 16);
    float h1 = __uint_as_float(h & 0xffff0000u);
    float l0 = f0 - h0, l1 = f1 - h1;
    asm("cvt.rn.bf16x2.f32 %0, %1, %2;" : "=r"(lp) : "f"(l1), "f"(l0));
    hp = h;
}
// split 16 values and store to Z smem (two 16B lines per half)
__device__ __forceinline__ void split_store16(const float* v, char* smem, uint32_t zoff) {
    uint32_t hp[8], lp[8];
    #pragma unroll
    for (int i = 0; i < 8; i++) split2(v[2 * i], v[2 * i + 1], hp[i], lp[i]);
    *(uint4*)(smem + ZHI + zoff)      = make_uint4(hp[0], hp[1], hp[2], hp[3]);
    *(uint4*)(smem + ZHI + zoff + 16) = make_uint4(hp[4], hp[5], hp[6], hp[7]);
    *(uint4*)(smem + ZLO + zoff)      = make_uint4(lp[0], lp[1], lp[2], lp[3]);
    *(uint4*)(smem + ZLO + zoff + 16) = make_uint4(lp[4], lp[5], lp[6], lp[7]);
}
// cp.async one W k-chunk (hi+lo, 128 rows x 32 k) into stage
__device__ __forceinline__ void cp_w_chunk(char* stg, const __nv_bfloat16* whi,
                                           const __nv_bfloat16* wlo, int n0, int k0, int tid) {
    uint32_t wb = smem_u32(stg + WHI);
    #pragma unroll
    for (int i = 0; i < 4; i++) {
        int tx = tid + i * 256;
        int part = tx >> 9, row = (tx >> 2) & 127, seg = tx & 3;
        const __nv_bfloat16* src = (part ? wlo : whi) + (size_t)(n0 + row) * D + k0 + seg * 8;
        cp16(wb + part * 10240 + row * ROWB + seg * 16, src);
    }
    cp_commit();
}

// ================= init / prep / ln / combine / gather =================
__global__ void k_init(const float* __restrict__ x) {
    int i = blockIdx.x * 256 + threadIdx.x;
    g_x[i] = x[i];
    g_agg[i] = 0u;
}

// weight prep: mats 0..8: l=m/3; r0: Wd=W1top-W1bot; r1: Wb=W1bot; r2: W2^T
// mat 9: ffnW1^T ; 10: ffnW2^T.  Image [n][k] row-major bf16 hi/lo.
__global__ void k_prep(const float* __restrict__ W1, const float* __restrict__ W2,
                       const float* __restrict__ fW1, const float* __restrict__ fW2,
                       __nv_bfloat16* __restrict__ img) {
    int m = blockIdx.y;
    int e = blockIdx.x * 256 + threadIdx.x;
    int n = e & 511, k = e >> 9;
    float w;
    if (m < 9) {
        int l = m / 3, r = m % 3;
        const float* base = W1 + (size_t)l * 2 * D * D;
        if (r == 0)      w = base[(size_t)k * D + n] - base[(size_t)(D + k) * D + n];
        else if (r == 1) w = base[(size_t)(D + k) * D + n];
        else             w = W2[((size_t)l * D + k) * D + n];
    } else if (m == 9)   w = fW1[(size_t)k * D + n];
    else                 w = fW2[(size_t)k * D + n];
    __nv_bfloat16 h = __float2bfloat16(w);
    __nv_bfloat16 lo = __float2bfloat16(w - __bfloat162float(h));
    size_t idx = (size_t)n * D + k;
    img[((size_t)m * 2) * (D * D) + idx]     = h;
    img[((size_t)m * 2 + 1) * (D * D) + idx] = lo;
}

__global__ __launch_bounds__(128) void k_ln(const float* __restrict__ x,
                                            const float* __restrict__ gamma,
                                            const float* __restrict__ beta,
                                            float* __restrict__ out) {
    __shared__ float red[8];
    int row = blockIdx.x;
    int t = threadIdx.x;
    float4 v = ((const float4*)(x + (size_t)row * D))[t];
    float s = v.x + v.y + v.z + v.w;
    #pragma unroll
    for (int o = 16; o > 0; o >>= 1) s += __shfl_xor_sync(0xffffffffu, s, o);
    if ((t & 31) == 0) red[t >> 5] = s;
    __syncthreads();
    if (t == 0) red[4] = red[0] + red[1] + red[2] + red[3];
    __syncthreads();
    float mu = red[4] * (1.0f / D);
    __syncthreads();
    float dx = v.x - mu, dy = v.y - mu, dz = v.z - mu, dw = v.w - mu;
    float q = dx * dx + dy * dy + dz * dz + dw * dw;
    #pragma unroll
    for (int o = 16; o > 0; o >>= 1) q += __shfl_xor_sync(0xffffffffu, q, o);
    if ((t & 31) == 0) red[t >> 5] = q;
    __syncthreads();
    if (t == 0) red[4] = red[0] + red[1] + red[2] + red[3];
    __syncthreads();
    float rstd = rsqrtf(red[4] * (1.0f / D) + 1e-5f);
    float4 g4 = ((const float4*)gamma)[t];
    float4 b4 = ((const float4*)beta)[t];
    float4 o4;
    o4.x = dx * rstd * g4.x + b4.x;
    o4.y = dy * rstd * g4.y + b4.y;
    o4.z = dz * rstd * g4.z + b4.z;
    o4.w = dw * rstd * g4.w + b4.w;
    ((float4*)(out + (size_t)row * D))[t] = o4;
}

__global__ void k_combine(const float* __restrict__ b2) {
    int i = blockIdx.x * 256 + threadIdx.x;
    unsigned u = g_agg[i];
    g_agg[i] = 0u;
    float v = (u == 0u) ? 0.0f : (fdec(u) + b2[i & (D - 1)]);
    g_x[i] = fmaxf(v, 0.0f) + g_x[i];
}

__global__ __launch_bounds__(128) void k_gather(const float* __restrict__ y,
                                                const int* __restrict__ sel,
                                                float* __restrict__ out) {
    int r = blockIdx.x;
    int b = r >> 7, s = r & (S_SEL - 1);
    int node = b * NPG + sel[b * S_SEL + s];
    ((float4*)(out + (size_t)r * D))[threadIdx.x] =
        ((const float4*)(y + (size_t)node * D))[threadIdx.x];
}

// ================= dense GEMM: out = op(H @ Wimg + bias [+res]) =================
// grid(x = D/128 = 4, y = M/128), 256 threads, 2 CTAs/SM
__global__ __launch_bounds__(256, 2) void k_mma_gemm(
    const float* __restrict__ Hm,
    const __nv_bfloat16* __restrict__ whi,
    const __nv_bfloat16* __restrict__ wlo,
    const float* __restrict__ bias,
    const float* __restrict__ res,
    float* __restrict__ out,
    int relu)
{
    extern __shared__ char smem[];
    int tid = threadIdx.x;
    int n0 = blockIdx.x * BN;
    int m0 = blockIdx.y * BM;

    int lane = tid & 31, wm = (tid >> 5) & 1, wn = tid >> 6;   // wm 0..1, wn 0..3
    int zrow = tid >> 1, half = tid & 1;
    const float* hrow = Hm + (size_t)(m0 + zrow) * D + half * 16;
    uint32_t zoff = zrow * ROWB + half * 32;

    uint32_t aoff = (uint32_t)(wm * 64 + (lane & 7) + ((lane >> 3) & 1) * 8) * ROWB
                  + ((lane >> 4) & 1) * 16;
    uint32_t boff = (uint32_t)(wn * 32 + (lane & 7) + ((lane >= 16) ? 8 : 0)) * ROWB
                  + ((lane >> 3) & 1) * 16;

    float acc[4][4][4] = {};

    // prologue: stage 0
    cp_w_chunk(smem, whi, wlo, n0, 0, tid);
    {
        float v[16];
        #pragma unroll
        for (int i = 0; i < 4; i++) *(float4*)(v + 4 * i) = *(const float4*)(hrow + 4 * i);
        split_store16(v, smem, zoff);
    }
    cp_wait0();
    __syncthreads();

    for (int c = 0; c < NCH; c++) {
        char* stg = smem + (c & 1) * STAGE;
        char* nstg = smem + ((c + 1) & 1) * STAGE;
        uint32_t zhi = smem_u32(stg + ZHI), zlo = smem_u32(stg + ZLO);
        uint32_t whb = smem_u32(stg + WHI), wlb = smem_u32(stg + WLO);

        float v[16];
        if (c + 1 < NCH) {
            cp_w_chunk(nstg, whi, wlo, n0, (c + 1) * BK, tid);
            const float* p = hrow + (c + 1) * BK;
            #pragma unroll
            for (int i = 0; i < 4; i++) *(float4*)(v + 4 * i) = *(const float4*)(p + 4 * i);
        }

        #pragma unroll
        for (int kh = 0; kh < 2; kh++) {
            uint32_t bh[2][4], bl[2][4];
            #pragma unroll
            for (int np = 0; np < 2; np++) {
                ldm_x4(bh[np], whb + boff + np * 16 * ROWB + kh * 32);
                ldm_x4(bl[np], wlb + boff + np * 16 * ROWB + kh * 32);
            }
            #pragma unroll
            for (int mf = 0; mf < 4; mf++) {
                uint32_t ah[4], al[4];
                ldm_x4(ah, zhi + aoff + mf * 16 * ROWB + kh * 32);
                ldm_x4(al, zlo + aoff + mf * 16 * ROWB + kh * 32);
                #pragma unroll
                for (int np = 0; np < 2; np++) {
                    #pragma unroll
                    for (int j = 0; j < 2; j++) {
                        float* d = acc[mf][np * 2 + j];
                        mma16816(d, ah, bh[np][2 * j], bh[np][2 * j + 1]);
                        mma16816(d, al, bh[np][2 * j], bh[np][2 * j + 1]);
                        mma16816(d, ah, bl[np][2 * j], bl[np][2 * j + 1]);
                    }
                }
            }
        }
        if (c + 1 < NCH) split_store16(v, nstg, zoff);
        cp_wait0();
        __syncthreads();
    }

    // epilogue
    #pragma unroll
    for (int mf = 0; mf < 4; mf++) {
        int r0 = m0 + wm * 64 + mf * 16 + (lane >> 2);
        int colb = n0 + wn * 32 + 2 * (lane & 3);
        #pragma unroll
        for (int nf = 0; nf < 4; nf++) {
            int col = colb + nf * 8;
            float2 bv = bias ? *(const float2*)(bias + col) : make_float2(0.f, 0.f);
            float c0 = acc[mf][nf][0] + bv.x, c1 = acc[mf][nf][1] + bv.y;
            float c2 = acc[mf][nf][2] + bv.x, c3 = acc[mf][nf][3] + bv.y;
            if (relu) {
                c0 = fmaxf(c0, 0.f); c1 = fmaxf(c1, 0.f);
                c2 = fmaxf(c2, 0.f); c3 = fmaxf(c3, 0.f);
            }
            if (res) {
                float2 r1v = *(const float2*)(res + (size_t)r0 * D + col);
                float2 r2v = *(const float2*)(res + (size_t)(r0 + 8) * D + col);
                c0 += r1v.x; c1 += r1v.y; c2 += r2v.x; c3 += r2v.y;
            }
            *(float2*)(out + (size_t)r0 * D + col) = make_float2(c0, c1);
            *(float2*)(out + (size_t)(r0 + 8) * D + col) = make_float2(c2, c3);
        }
    }
}

// ================= edge GEMM: relu(A[dst]+B[src]) @ W2img -> gated atomicMax =================
// grid(x = D/128 = 4, y = E/128 = 1024), 256 threads, 2 CTAs/SM
__global__ __launch_bounds__(256, 2) void k_mma_edge(
    const __nv_bfloat16* __restrict__ whi,
    const __nv_bfloat16* __restrict__ wlo,
    const int* __restrict__ src,
    const int* __restrict__ dst,
    const float* __restrict__ b2,
    unsigned* __restrict__ agg)
{
    extern __shared__ char smem[];
    int tid = threadIdx.x;
    int n0 = blockIdx.x * BN;
    int e0 = blockIdx.y * BM;

    int* sDst = (int*)(smem + SM_IDX);
    int* sSrc = (int*)(smem + SM_IDX + 512);
    if (tid < 128) sDst[tid] = dst[e0 + tid];
    else           sSrc[tid - 128] = src[e0 + tid - 128];

    int lane = tid & 31, wm = (tid >> 5) & 1, wn = tid >> 6;
    int zrow = tid >> 1, half = tid & 1;
    uint32_t zoff = zrow * ROWB + half * 32;

    uint32_t aoff = (uint32_t)(wm * 64 + (lane & 7) + ((lane >> 3) & 1) * 8) * ROWB
                  + ((lane >> 4) & 1) * 16;
    uint32_t boff = (uint32_t)(wn * 32 + (lane & 7) + ((lane >= 16) ? 8 : 0)) * ROWB
                  + ((lane >> 3) & 1) * 16;

    float acc[4][4][4] = {};

    cp_w_chunk(smem, whi, wlo, n0, 0, tid);
    __syncthreads();   // sDst/sSrc visible
    const float* ap = g_A + (size_t)sDst[zrow] * D + half * 16;
    const float* bp = g_B + (size_t)sSrc[zrow] * D + half * 16;
    {
        float v[16];
        #pragma unroll
        for (int i = 0; i < 4; i++) {
            float4 a = *(const float4*)(ap + 4 * i);
            float4 b = *(const float4*)(bp + 4 * i);
            v[4 * i + 0] = fmaxf(a.x + b.x, 0.f); v[4 * i + 1] = fmaxf(a.y + b.y, 0.f);
            v[4 * i + 2] = fmaxf(a.z + b.z, 0.f); v[4 * i + 3] = fmaxf(a.w + b.w, 0.f);
        }
        split_store16(v, smem, zoff);
    }
    cp_wait0();
    __syncthreads();

    for (int c = 0; c < NCH; c++) {
        char* stg = smem + (c & 1) * STAGE;
        char* nstg = smem + ((c + 1) & 1) * STAGE;
        uint32_t zhi = smem_u32(stg + ZHI), zlo = smem_u32(stg + ZLO);
        uint32_t whb = smem_u32(stg + WHI), wlb = smem_u32(stg + WLO);

        float v[16];
        if (c + 1 < NCH) {
            cp_w_chunk(nstg, whi, wlo, n0, (c + 1) * BK, tid);
            int k1 = (c + 1) * BK;
            #pragma unroll
            for (int i = 0; i < 4; i++) {
                float4 a = *(const float4*)(ap + k1 + 4 * i);
                float4 b = *(const float4*)(bp + k1 + 4 * i);
                v[4 * i + 0] = fmaxf(a.x + b.x, 0.f); v[4 * i + 1] = fmaxf(a.y + b.y, 0.f);
                v[4 * i + 2] = fmaxf(a.z + b.z, 0.f); v[4 * i + 3] = fmaxf(a.w + b.w, 0.f);
            }
        }

        #pragma unroll
        for (int kh = 0; kh < 2; kh++) {
            uint32_t bh[2][4], bl[2][4];
            #pragma unroll
            for (int np = 0; np < 2; np++) {
                ldm_x4(bh[np], whb + boff + np * 16 * ROWB + kh * 32);
                ldm_x4(bl[np], wlb + boff + np * 16 * ROWB + kh * 32);
            }
            #pragma unroll
            for (int mf = 0; mf < 4; mf++) {
                uint32_t ah[4], al[4];
                ldm_x4(ah, zhi + aoff + mf * 16 * ROWB + kh * 32);
                ldm_x4(al, zlo + aoff + mf * 16 * ROWB + kh * 32);
                #pragma unroll
                for (int np = 0; np < 2; np++) {
                    #pragma unroll
                    for (int j = 0; j < 2; j++) {
                        float* d = acc[mf][np * 2 + j];
                        mma16816(d, ah, bh[np][2 * j], bh[np][2 * j + 1]);
                        mma16816(d, al, bh[np][2 * j], bh[np][2 * j + 1]);
                        mma16816(d, ah, bl[np][2 * j], bl[np][2 * j + 1]);
                    }
                }
            }
        }
        if (c + 1 < NCH) split_store16(v, nstg, zoff);
        cp_wait0();
        __syncthreads();
    }

    // epilogue: gated atomic segment-max.
    // Values v with v + b2[col] <= 0 can never affect relu(max+b2): skip them.
    #pragma unroll
    for (int mf = 0; mf < 4; mf++) {
        int r0 = wm * 64 + mf * 16 + (lane >> 2);
        int colb = n0 + wn * 32 + 2 * (lane & 3);
        unsigned* p0 = agg + (size_t)sDst[r0] * D + colb;
        unsigned* p1 = agg + (size_t)sDst[r0 + 8] * D + colb;
        #pragma unroll
        for (int nf = 0; nf < 4; nf++) {
            float2 bv = *(const float2*)(b2 + colb + nf * 8);
            float t0 = -bv.x, t1 = -bv.y;
            if (acc[mf][nf][0] > t0) atomicMax(p0 + nf * 8,     fenc(acc[mf][nf][0]));
            if (acc[mf][nf][1] > t1) atomicMax(p0 + nf * 8 + 1, fenc(acc[mf][nf][1]));
            if (acc[mf][nf][2] > t0) atomicMax(p1 + nf * 8,     fenc(acc[mf][nf][2]));
            if (acc[mf][nf][3] > t1) atomicMax(p1 + nf * 8 + 1, fenc(acc[mf][nf][3]));
        }
    }
}

// ================= host launcher =================
extern "C" void kernel_launch(void* const* d_in, const int* in_sizes, int n_in,
                              void* d_out, int out_size) {
    const float* x       = (const float*)d_in[0];
    const int*   eidx    = (const int*)d_in[1];
    const int*   sel     = (const int*)d_in[2];
    const float* conv_W1 = (const float*)d_in[4];
    const float* conv_b1 = (const float*)d_in[5];
    const float* conv_W2 = (const float*)d_in[6];
    const float* conv_b2 = (const float*)d_in[7];
    const float* ln1_g   = (const float*)d_in[8];
    const float* ln1_b   = (const float*)d_in[9];
    const float* ln2_g   = (const float*)d_in[10];
    const float* ln2_b   = (const float*)d_in[11];
    const float* ffn_W1  = (const float*)d_in[12];
    const float* ffn_b1  = (const float*)d_in[13];
    const float* ffn_W2  = (const float*)d_in[14];
    const float* ffn_b2  = (const float*)d_in[15];
    float* out = (float*)d_out;

    const int* src = eidx;
    const int* dst = eidx + E_EDGES;

    float *gx, *gh, *ga, *gb;
    unsigned* gagg;
    __nv_bfloat16* gw;
    cudaGetSymbolAddress((void**)&gx, g_x);
    cudaGetSymbolAddress((void**)&gh, g_h);
    cudaGetSymbolAddress((void**)&ga, g_A);
    cudaGetSymbolAddress((void**)&gb, g_B);
    cudaGetSymbolAddress((void**)&gagg, g_agg);
    cudaGetSymbolAddress((void**)&gw, g_Wimg);

    cudaFuncSetAttribute(k_mma_gemm, cudaFuncAttributeMaxDynamicSharedMemorySize, SMEM_GEMM);
    cudaFuncSetAttribute(k_mma_edge, cudaFuncAttributeMaxDynamicSharedMemorySize, SMEM_EDGE);

    auto WH = [&](int m) { return gw + (size_t)m * 2 * (D * D); };
    auto WL = [&](int m) { return gw + ((size_t)m * 2 + 1) * (D * D); };

    const int ND = N_NODES * D;

    k_init<<<ND / 256, 256>>>(x);
    {
        dim3 grid(1024, NMAT);
        k_prep<<<grid, 256>>>(conv_W1, conv_W2, ffn_W1, ffn_W2, gw);
    }

    dim3 ggemm(D / BN, N_NODES / BM);   // (4, 64)
    dim3 gedge(D / BN, E_EDGES / BM);   // (4, 1024)

    for (int l = 0; l < L_LAYERS; l++) {
        k_ln<<<N_NODES, 128>>>(gx, ln1_g, ln1_b, gh);
        k_mma_gemm<<<ggemm, 256, SMEM_GEMM>>>(gh, WH(l * 3 + 0), WL(l * 3 + 0),
                                              conv_b1 + (size_t)l * D, nullptr, ga, 0);
        k_mma_gemm<<<ggemm, 256, SMEM_GEMM>>>(gh, WH(l * 3 + 1), WL(l * 3 + 1),
                                              nullptr, nullptr, gb, 0);
        k_mma_edge<<<gedge, 256, SMEM_EDGE>>>(WH(l * 3 + 2), WL(l * 3 + 2), src, dst,
                                              conv_b2 + (size_t)l * D, gagg);
        k_combine<<<ND / 256, 256>>>(conv_b2 + (size_t)l * D);
    }

    k_ln<<<N_NODES, 128>>>(gx, ln2_g, ln2_b, gh);
    k_mma_gemm<<<ggemm, 256, SMEM_GEMM>>>(gh, WH(9), WL(9), ffn_b1, nullptr, ga, 1);
    k_mma_gemm<<<ggemm, 256, SMEM_GEMM>>>(ga, WH(10), WL(10), ffn_b2, gx, gh, 0);
    k_gather<<<B_GR * S_SEL, 128>>>(gh, sel, out);
}

// round 5
// speedup vs baseline: 1.2985x; 1.2985x over previous
#include <cuda_runtime.h>
#include <cuda_bf16.h>
#include <cuda_fp16.h>
#include <cstdint>

// Problem constants (fixed shapes)
constexpr int N_NODES = 8192;
constexpr int D = 512;
constexpr int E_EDGES = 131072;
constexpr int B_GR = 16;
constexpr int NPG = 512;
constexpr int S_SEL = 128;
constexpr int L_LAYERS = 3;

// GEMM tiling
constexpr int BM = 128;
constexpr int BN = 128;
constexpr int BK = 32;             // k-chunk
constexpr int NCH = D / BK;        // 16 chunks
constexpr int NMAT = 11;

// dense (bf16 3-term) smem stage layout: padded rows of 80B
constexpr int ROWB = 80;
constexpr int ZHI = 0;                      // 128*80 = 10240
constexpr int ZLO = 10240;
constexpr int WHI = 20480;
constexpr int WLO = 30720;
constexpr int STAGE = 40960;
constexpr int SMEM_GEMM = 2 * STAGE;

// edge (fp16 1-term) smem stage layout
constexpr int EZ = 0;                       // 128*80 = 10240
constexpr int EW = 10240;
constexpr int ESTAGE = 20480;
constexpr int ESM_IDX = 2 * ESTAGE;         // sDst(512)+sSrc(512)
constexpr int SMEM_EDGE = 2 * ESTAGE + 1024;

// -------- static device scratch --------
__device__ float    g_x[N_NODES * D];
__device__ float    g_h[N_NODES * D];
__device__ float    g_A[N_NODES * D];
__device__ float    g_B[N_NODES * D];
__device__ unsigned g_agg[N_NODES * D];
// bf16 weight images: [mat][hi/lo][n][k] row-major (k contiguous)
__device__ __align__(16) __nv_bfloat16 g_Wimg[(size_t)NMAT * 2 * D * D];
// fp16 W2 images for the 3 edge layers: [l][n][k]
__device__ __align__(16) __half g_W2h[(size_t)L_LAYERS * D * D];

// ---------------- helpers ----------------
__device__ __forceinline__ unsigned fenc(float f) {
    unsigned b = __float_as_uint(f);
    return (b & 0x80000000u) ? ~b : (b | 0x80000000u);
}
__device__ __forceinline__ float fdec(unsigned u) {
    unsigned b = (u & 0x80000000u) ? (u & 0x7fffffffu) : ~u;
    return __uint_as_float(b);
}
__device__ __forceinline__ uint32_t smem_u32(const void* p) {
    uint32_t a;
    asm("{ .reg .u64 t; cvta.to.shared.u64 t, %1; cvt.u32.u64 %0, t; }" : "=r"(a) : "l"(p));
    return a;
}
__device__ __forceinline__ void cp16(uint32_t dst, const void* src) {
    asm volatile("cp.async.cg.shared.global [%0], [%1], 16;" :: "r"(dst), "l"(src) : "memory");
}
__device__ __forceinline__ void cp_commit() {
    asm volatile("cp.async.commit_group;" ::: "memory");
}
__device__ __forceinline__ void cp_wait0() {
    asm volatile("cp.async.wait_group 0;" ::: "memory");
}
__device__ __forceinline__ void ldm_x4(uint32_t* r, uint32_t addr) {
    asm volatile("ldmatrix.sync.aligned.m8n8.x4.shared.b16 {%0,%1,%2,%3}, [%4];"
                 : "=r"(r[0]), "=r"(r[1]), "=r"(r[2]), "=r"(r[3]) : "r"(addr));
}
__device__ __forceinline__ void mma_bf(float* d, const uint32_t* a, uint32_t b0, uint32_t b1) {
    asm volatile(
        "mma.sync.aligned.m16n8k16.row.col.f32.bf16.bf16.f32 "
        "{%0,%1,%2,%3}, {%4,%5,%6,%7}, {%8,%9}, {%0,%1,%2,%3};"
        : "+f"(d[0]), "+f"(d[1]), "+f"(d[2]), "+f"(d[3])
        : "r"(a[0]), "r"(a[1]), "r"(a[2]), "r"(a[3]), "r"(b0), "r"(b1));
}
__device__ __forceinline__ void mma_h(float* d, const uint32_t* a, uint32_t b0, uint32_t b1) {
    asm volatile(
        "mma.sync.aligned.m16n8k16.row.col.f32.f16.f16.f32 "
        "{%0,%1,%2,%3}, {%4,%5,%6,%7}, {%8,%9}, {%0,%1,%2,%3};"
        : "+f"(d[0]), "+f"(d[1]), "+f"(d[2]), "+f"(d[3])
        : "r"(a[0]), "r"(a[1]), "r"(a[2]), "r"(a[3]), "r"(b0), "r"(b1));
}
// split 2 fp32 -> packed bf16x2 hi + bf16x2 lo
__device__ __forceinline__ void split2(float f0, float f1, uint32_t& hp, uint32_t& lp) {
    uint32_t h;
    asm("cvt.rn.bf16x2.f32 %0, %1, %2;" : "=r"(h) : "f"(f1), "f"(f0));
    float h0 = __uint_as_float(h << 16);
    float h1 = __uint_as_float(h & 0xffff0000u);
    float l0 = f0 - h0, l1 = f1 - h1;
    asm("cvt.rn.bf16x2.f32 %0, %1, %2;" : "=r"(lp) : "f"(l1), "f"(l0));
    hp = h;
}
__device__ __forceinline__ void split_store16(const float* v, char* smem, uint32_t zoff) {
    uint32_t hp[8], lp[8];
    #pragma unroll
    for (int i = 0; i < 8; i++) split2(v[2 * i], v[2 * i + 1], hp[i], lp[i]);
    *(uint4*)(smem + ZHI + zoff)      = make_uint4(hp[0], hp[1], hp[2], hp[3]);
    *(uint4*)(smem + ZHI + zoff + 16) = make_uint4(hp[4], hp[5], hp[6], hp[7]);
    *(uint4*)(smem + ZLO + zoff)      = make_uint4(lp[0], lp[1], lp[2], lp[3]);
    *(uint4*)(smem + ZLO + zoff + 16) = make_uint4(lp[4], lp[5], lp[6], lp[7]);
}
// fp16 store of 16 values (one thread-half row segment, 32B)
__device__ __forceinline__ void h_store16(const float* v, char* smem, uint32_t zoff) {
    uint32_t p[8];
    #pragma unroll
    for (int i = 0; i < 8; i++)
        asm("cvt.rn.f16x2.f32 %0, %1, %2;" : "=r"(p[i]) : "f"(v[2 * i + 1]), "f"(v[2 * i]));
    *(uint4*)(smem + EZ + zoff)      = make_uint4(p[0], p[1], p[2], p[3]);
    *(uint4*)(smem + EZ + zoff + 16) = make_uint4(p[4], p[5], p[6], p[7]);
}
// cp.async one bf16 W k-chunk (hi+lo, 128 rows x 32 k) into dense stage
__device__ __forceinline__ void cp_w_chunk(char* stg, const __nv_bfloat16* whi,
                                           const __nv_bfloat16* wlo, int n0, int k0, int tid) {
    uint32_t wb = smem_u32(stg + WHI);
    #pragma unroll
    for (int i = 0; i < 4; i++) {
        int tx = tid + i * 256;
        int part = tx >> 9, row = (tx >> 2) & 127, seg = tx & 3;
        const __nv_bfloat16* src = (part ? wlo : whi) + (size_t)(n0 + row) * D + k0 + seg * 8;
        cp16(wb + part * 10240 + row * ROWB + seg * 16, src);
    }
    cp_commit();
}
// cp.async one fp16 W k-chunk (128 rows x 32 k) into edge stage
__device__ __forceinline__ void cp_w_chunk_h(char* stg, const __half* w,
                                             int n0, int k0, int tid) {
    uint32_t wb = smem_u32(stg + EW);
    #pragma unroll
    for (int i = 0; i < 2; i++) {
        int tx = tid + i * 256;
        int row = tx >> 2, seg = tx & 3;
        const __half* src = w + (size_t)(n0 + row) * D + k0 + seg * 8;
        cp16(wb + row * ROWB + seg * 16, src);
    }
    cp_commit();
}

// ================= init / prep / ln / combine / gather =================
__global__ void k_init(const float* __restrict__ x) {
    int i = blockIdx.x * 256 + threadIdx.x;
    g_x[i] = x[i];
    g_agg[i] = 0u;
}

// bf16 weight prep: mats 0..8: l=m/3; r0: Wd=W1top-W1bot; r1: Wb=W1bot; r2: W2^T
// mat 9: ffnW1^T ; 10: ffnW2^T.  Image [n][k] row-major bf16 hi/lo.
__global__ void k_prep(const float* __restrict__ W1, const float* __restrict__ W2,
                       const float* __restrict__ fW1, const float* __restrict__ fW2,
                       __nv_bfloat16* __restrict__ img) {
    int m = blockIdx.y;
    int e = blockIdx.x * 256 + threadIdx.x;
    int n = e & 511, k = e >> 9;
    float w;
    if (m < 9) {
        int l = m / 3, r = m % 3;
        const float* base = W1 + (size_t)l * 2 * D * D;
        if (r == 0)      w = base[(size_t)k * D + n] - base[(size_t)(D + k) * D + n];
        else if (r == 1) w = base[(size_t)(D + k) * D + n];
        else             w = W2[((size_t)l * D + k) * D + n];
    } else if (m == 9)   w = fW1[(size_t)k * D + n];
    else                 w = fW2[(size_t)k * D + n];
    __nv_bfloat16 h = __float2bfloat16(w);
    __nv_bfloat16 lo = __float2bfloat16(w - __bfloat162float(h));
    size_t idx = (size_t)n * D + k;
    img[((size_t)m * 2) * (D * D) + idx]     = h;
    img[((size_t)m * 2 + 1) * (D * D) + idx] = lo;
}

// fp16 W2 image: [l][n][k] = fp16(W2[l][k][n])
__global__ void k_prep16(const float* __restrict__ W2, __half* __restrict__ img) {
    int l = blockIdx.y;
    int e = blockIdx.x * 256 + threadIdx.x;
    int n = e & 511, k = e >> 9;
    float w = W2[((size_t)l * D + k) * D + n];
    img[(size_t)l * D * D + (size_t)n * D + k] = __float2half(w);
}

__global__ __launch_bounds__(128) void k_ln(const float* __restrict__ x,
                                            const float* __restrict__ gamma,
                                            const float* __restrict__ beta,
                                            float* __restrict__ out) {
    __shared__ float red[8];
    int row = blockIdx.x;
    int t = threadIdx.x;
    float4 v = ((const float4*)(x + (size_t)row * D))[t];
    float s = v.x + v.y + v.z + v.w;
    #pragma unroll
    for (int o = 16; o > 0; o >>= 1) s += __shfl_xor_sync(0xffffffffu, s, o);
    if ((t & 31) == 0) red[t >> 5] = s;
    __syncthreads();
    if (t == 0) red[4] = red[0] + red[1] + red[2] + red[3];
    __syncthreads();
    float mu = red[4] * (1.0f / D);
    __syncthreads();
    float dx = v.x - mu, dy = v.y - mu, dz = v.z - mu, dw = v.w - mu;
    float q = dx * dx + dy * dy + dz * dz + dw * dw;
    #pragma unroll
    for (int o = 16; o > 0; o >>= 1) q += __shfl_xor_sync(0xffffffffu, q, o);
    if ((t & 31) == 0) red[t >> 5] = q;
    __syncthreads();
    if (t == 0) red[4] = red[0] + red[1] + red[2] + red[3];
    __syncthreads();
    float rstd = rsqrtf(red[4] * (1.0f / D) + 1e-5f);
    float4 g4 = ((const float4*)gamma)[t];
    float4 b4 = ((const float4*)beta)[t];
    float4 o4;
    o4.x = dx * rstd * g4.x + b4.x;
    o4.y = dy * rstd * g4.y + b4.y;
    o4.z = dz * rstd * g4.z + b4.z;
    o4.w = dw * rstd * g4.w + b4.w;
    ((float4*)(out + (size_t)row * D))[t] = o4;
}

__global__ void k_combine(const float* __restrict__ b2) {
    int i = blockIdx.x * 256 + threadIdx.x;
    unsigned u = g_agg[i];
    g_agg[i] = 0u;
    float v = (u == 0u) ? 0.0f : (fdec(u) + b2[i & (D - 1)]);
    g_x[i] = fmaxf(v, 0.0f) + g_x[i];
}

__global__ __launch_bounds__(128) void k_gather(const float* __restrict__ y,
                                                const int* __restrict__ sel,
                                                float* __restrict__ out) {
    int r = blockIdx.x;
    int b = r >> 7, s = r & (S_SEL - 1);
    int node = b * NPG + sel[b * S_SEL + s];
    ((float4*)(out + (size_t)r * D))[threadIdx.x] =
        ((const float4*)(y + (size_t)node * D))[threadIdx.x];
}

// ================= dense GEMM (bf16 3-term): out = op(H @ Wimg + bias [+res]) =================
// grid(x = D/128 = 4, y = M/128), 256 threads, 2 CTAs/SM
__global__ __launch_bounds__(256, 2) void k_mma_gemm(
    const float* __restrict__ Hm,
    const __nv_bfloat16* __restrict__ whi,
    const __nv_bfloat16* __restrict__ wlo,
    const float* __restrict__ bias,
    const float* __restrict__ res,
    float* __restrict__ out,
    int relu)
{
    extern __shared__ char smem[];
    int tid = threadIdx.x;
    int n0 = blockIdx.x * BN;
    int m0 = blockIdx.y * BM;

    int lane = tid & 31, wm = (tid >> 5) & 1, wn = tid >> 6;
    int zrow = tid >> 1, half = tid & 1;
    const float* hrow = Hm + (size_t)(m0 + zrow) * D + half * 16;
    uint32_t zoff = zrow * ROWB + half * 32;

    uint32_t aoff = (uint32_t)(wm * 64 + (lane & 7) + ((lane >> 3) & 1) * 8) * ROWB
                  + ((lane >> 4) & 1) * 16;
    uint32_t boff = (uint32_t)(wn * 32 + (lane & 7) + ((lane >= 16) ? 8 : 0)) * ROWB
                  + ((lane >> 3) & 1) * 16;

    float acc[4][4][4] = {};

    cp_w_chunk(smem, whi, wlo, n0, 0, tid);
    {
        float v[16];
        #pragma unroll
        for (int i = 0; i < 4; i++) *(float4*)(v + 4 * i) = *(const float4*)(hrow + 4 * i);
        split_store16(v, smem, zoff);
    }
    cp_wait0();
    __syncthreads();

    for (int c = 0; c < NCH; c++) {
        char* stg = smem + (c & 1) * STAGE;
        char* nstg = smem + ((c + 1) & 1) * STAGE;
        uint32_t zhi = smem_u32(stg + ZHI), zlo = smem_u32(stg + ZLO);
        uint32_t whb = smem_u32(stg + WHI), wlb = smem_u32(stg + WLO);

        float v[16];
        if (c + 1 < NCH) {
            cp_w_chunk(nstg, whi, wlo, n0, (c + 1) * BK, tid);
            const float* p = hrow + (c + 1) * BK;
            #pragma unroll
            for (int i = 0; i < 4; i++) *(float4*)(v + 4 * i) = *(const float4*)(p + 4 * i);
        }

        #pragma unroll
        for (int kh = 0; kh < 2; kh++) {
            uint32_t bh[2][4], bl[2][4];
            #pragma unroll
            for (int np = 0; np < 2; np++) {
                ldm_x4(bh[np], whb + boff + np * 16 * ROWB + kh * 32);
                ldm_x4(bl[np], wlb + boff + np * 16 * ROWB + kh * 32);
            }
            #pragma unroll
            for (int mf = 0; mf < 4; mf++) {
                uint32_t ah[4], al[4];
                ldm_x4(ah, zhi + aoff + mf * 16 * ROWB + kh * 32);
                ldm_x4(al, zlo + aoff + mf * 16 * ROWB + kh * 32);
                #pragma unroll
                for (int np = 0; np < 2; np++) {
                    #pragma unroll
                    for (int j = 0; j < 2; j++) {
                        float* d = acc[mf][np * 2 + j];
                        mma_bf(d, ah, bh[np][2 * j], bh[np][2 * j + 1]);
                        mma_bf(d, al, bh[np][2 * j], bh[np][2 * j + 1]);
                        mma_bf(d, ah, bl[np][2 * j], bl[np][2 * j + 1]);
                    }
                }
            }
        }
        if (c + 1 < NCH) split_store16(v, nstg, zoff);
        cp_wait0();
        __syncthreads();
    }

    #pragma unroll
    for (int mf = 0; mf < 4; mf++) {
        int r0 = m0 + wm * 64 + mf * 16 + (lane >> 2);
        int colb = n0 + wn * 32 + 2 * (lane & 3);
        #pragma unroll
        for (int nf = 0; nf < 4; nf++) {
            int col = colb + nf * 8;
            float2 bv = bias ? *(const float2*)(bias + col) : make_float2(0.f, 0.f);
            float c0 = acc[mf][nf][0] + bv.x, c1 = acc[mf][nf][1] + bv.y;
            float c2 = acc[mf][nf][2] + bv.x, c3 = acc[mf][nf][3] + bv.y;
            if (relu) {
                c0 = fmaxf(c0, 0.f); c1 = fmaxf(c1, 0.f);
                c2 = fmaxf(c2, 0.f); c3 = fmaxf(c3, 0.f);
            }
            if (res) {
                float2 r1v = *(const float2*)(res + (size_t)r0 * D + col);
                float2 r2v = *(const float2*)(res + (size_t)(r0 + 8) * D + col);
                c0 += r1v.x; c1 += r1v.y; c2 += r2v.x; c3 += r2v.y;
            }
            *(float2*)(out + (size_t)r0 * D + col) = make_float2(c0, c1);
            *(float2*)(out + (size_t)(r0 + 8) * D + col) = make_float2(c2, c3);
        }
    }
}

// ================= edge GEMM (fp16 1-term): relu(A[dst]+B[src]) @ W2h -> gated atomicMax =================
// grid(x = D/128 = 4, y = E/128 = 1024), 256 threads, 2 CTAs/SM
__global__ __launch_bounds__(256, 2) void k_mma_edge(
    const __half* __restrict__ w16,
    const int* __restrict__ src,
    const int* __restrict__ dst,
    const float* __restrict__ b2,
    unsigned* __restrict__ agg)
{
    extern __shared__ char smem[];
    int tid = threadIdx.x;
    int n0 = blockIdx.x * BN;
    int e0 = blockIdx.y * BM;

    int* sDst = (int*)(smem + ESM_IDX);
    int* sSrc = (int*)(smem + ESM_IDX + 512);
    if (tid < 128) sDst[tid] = dst[e0 + tid];
    else           sSrc[tid - 128] = src[e0 + tid - 128];

    int lane = tid & 31, wm = (tid >> 5) & 1, wn = tid >> 6;
    int zrow = tid >> 1, half = tid & 1;
    uint32_t zoff = zrow * ROWB + half * 32;

    uint32_t aoff = (uint32_t)(wm * 64 + (lane & 7) + ((lane >> 3) & 1) * 8) * ROWB
                  + ((lane >> 4) & 1) * 16;
    uint32_t boff = (uint32_t)(wn * 32 + (lane & 7) + ((lane >= 16) ? 8 : 0)) * ROWB
                  + ((lane >> 3) & 1) * 16;

    float acc[4][4][4] = {};

    cp_w_chunk_h(smem, w16, n0, 0, tid);
    __syncthreads();   // sDst/sSrc visible
    const float* ap = g_A + (size_t)sDst[zrow] * D + half * 16;
    const float* bp = g_B + (size_t)sSrc[zrow] * D + half * 16;
    {
        float v[16];
        #pragma unroll
        for (int i = 0; i < 4; i++) {
            float4 a = *(const float4*)(ap + 4 * i);
            float4 b = *(const float4*)(bp + 4 * i);
            v[4 * i + 0] = fmaxf(a.x + b.x, 0.f); v[4 * i + 1] = fmaxf(a.y + b.y, 0.f);
            v[4 * i + 2] = fmaxf(a.z + b.z, 0.f); v[4 * i + 3] = fmaxf(a.w + b.w, 0.f);
        }
        h_store16(v, smem, zoff);
    }
    cp_wait0();
    __syncthreads();

    for (int c = 0; c < NCH; c++) {
        char* stg = smem + (c & 1) * ESTAGE;
        char* nstg = smem + ((c + 1) & 1) * ESTAGE;
        uint32_t zb = smem_u32(stg + EZ);
        uint32_t wbb = smem_u32(stg + EW);

        float v[16];
        if (c + 1 < NCH) {
            cp_w_chunk_h(nstg, w16, n0, (c + 1) * BK, tid);
            int k1 = (c + 1) * BK;
            #pragma unroll
            for (int i = 0; i < 4; i++) {
                float4 a = *(const float4*)(ap + k1 + 4 * i);
                float4 b = *(const float4*)(bp + k1 + 4 * i);
                v[4 * i + 0] = fmaxf(a.x + b.x, 0.f); v[4 * i + 1] = fmaxf(a.y + b.y, 0.f);
                v[4 * i + 2] = fmaxf(a.z + b.z, 0.f); v[4 * i + 3] = fmaxf(a.w + b.w, 0.f);
            }
        }

        #pragma unroll
        for (int kh = 0; kh < 2; kh++) {
            uint32_t bh[2][4];
            #pragma unroll
            for (int np = 0; np < 2; np++)
                ldm_x4(bh[np], wbb + boff + np * 16 * ROWB + kh * 32);
            #pragma unroll
            for (int mf = 0; mf < 4; mf++) {
                uint32_t ah[4];
                ldm_x4(ah, zb + aoff + mf * 16 * ROWB + kh * 32);
                #pragma unroll
                for (int np = 0; np < 2; np++) {
                    #pragma unroll
                    for (int j = 0; j < 2; j++)
                        mma_h(acc[mf][np * 2 + j], ah, bh[np][2 * j], bh[np][2 * j + 1]);
                }
            }
        }
        if (c + 1 < NCH) h_store16(v, nstg, zoff);
        cp_wait0();
        __syncthreads();
    }

    // epilogue: gated atomic segment-max (v + b2 <= 0 can never affect relu(max+b2))
    #pragma unroll
    for (int mf = 0; mf < 4; mf++) {
        int r0 = wm * 64 + mf * 16 + (lane >> 2);
        int colb = n0 + wn * 32 + 2 * (lane & 3);
        unsigned* p0 = agg + (size_t)sDst[r0] * D + colb;
        unsigned* p1 = agg + (size_t)sDst[r0 + 8] * D + colb;
        #pragma unroll
        for (int nf = 0; nf < 4; nf++) {
            float2 bv = *(const float2*)(b2 + colb + nf * 8);
            float t0 = -bv.x, t1 = -bv.y;
            if (acc[mf][nf][0] > t0) atomicMax(p0 + nf * 8,     fenc(acc[mf][nf][0]));
            if (acc[mf][nf][1] > t1) atomicMax(p0 + nf * 8 + 1, fenc(acc[mf][nf][1]));
            if (acc[mf][nf][2] > t0) atomicMax(p1 + nf * 8,     fenc(acc[mf][nf][2]));
            if (acc[mf][nf][3] > t1) atomicMax(p1 + nf * 8 + 1, fenc(acc[mf][nf][3]));
        }
    }
}

// ================= host launcher =================
extern "C" void kernel_launch(void* const* d_in, const int* in_sizes, int n_in,
                              void* d_out, int out_size) {
    const float* x       = (const float*)d_in[0];
    const int*   eidx    = (const int*)d_in[1];
    const int*   sel     = (const int*)d_in[2];
    const float* conv_W1 = (const float*)d_in[4];
    const float* conv_b1 = (const float*)d_in[5];
    const float* conv_W2 = (const float*)d_in[6];
    const float* conv_b2 = (const float*)d_in[7];
    const float* ln1_g   = (const float*)d_in[8];
    const float* ln1_b   = (const float*)d_in[9];
    const float* ln2_g   = (const float*)d_in[10];
    const float* ln2_b   = (const float*)d_in[11];
    const float* ffn_W1  = (const float*)d_in[12];
    const float* ffn_b1  = (const float*)d_in[13];
    const float* ffn_W2  = (const float*)d_in[14];
    const float* ffn_b2  = (const float*)d_in[15];
    float* out = (float*)d_out;

    const int* src = eidx;
    const int* dst = eidx + E_EDGES;

    float *gx, *gh, *ga, *gb;
    unsigned* gagg;
    __nv_bfloat16* gw;
    __half* gw16;
    cudaGetSymbolAddress((void**)&gx, g_x);
    cudaGetSymbolAddress((void**)&gh, g_h);
    cudaGetSymbolAddress((void**)&ga, g_A);
    cudaGetSymbolAddress((void**)&gb, g_B);
    cudaGetSymbolAddress((void**)&gagg, g_agg);
    cudaGetSymbolAddress((void**)&gw, g_Wimg);
    cudaGetSymbolAddress((void**)&gw16, g_W2h);

    cudaFuncSetAttribute(k_mma_gemm, cudaFuncAttributeMaxDynamicSharedMemorySize, SMEM_GEMM);
    cudaFuncSetAttribute(k_mma_edge, cudaFuncAttributeMaxDynamicSharedMemorySize, SMEM_EDGE);

    auto WH = [&](int m) { return gw + (size_t)m * 2 * (D * D); };
    auto WL = [&](int m) { return gw + ((size_t)m * 2 + 1) * (D * D); };

    const int ND = N_NODES * D;

    k_init<<<ND / 256, 256>>>(x);
    {
        dim3 grid(1024, NMAT);
        k_prep<<<grid, 256>>>(conv_W1, conv_W2, ffn_W1, ffn_W2, gw);
    }
    {
        dim3 grid(1024, L_LAYERS);
        k_prep16<<<grid, 256>>>(conv_W2, gw16);
    }

    dim3 ggemm(D / BN, N_NODES / BM);   // (4, 64)
    dim3 gedge(D / BN, E_EDGES / BM);   // (4, 1024)

    for (int l = 0; l < L_LAYERS; l++) {
        k_ln<<<N_NODES, 128>>>(gx, ln1_g, ln1_b, gh);
        k_mma_gemm<<<ggemm, 256, SMEM_GEMM>>>(gh, WH(l * 3 + 0), WL(l * 3 + 0),
                                              conv_b1 + (size_t)l * D, nullptr, ga, 0);
        k_mma_gemm<<<ggemm, 256, SMEM_GEMM>>>(gh, WH(l * 3 + 1), WL(l * 3 + 1),
                                              nullptr, nullptr, gb, 0);
        k_mma_edge<<<gedge, 256, SMEM_EDGE>>>(gw16 + (size_t)l * D * D, src, dst,
                                              conv_b2 + (size_t)l * D, gagg);
        k_combine<<<ND / 256, 256>>>(conv_b2 + (size_t)l * D);
    }

    k_ln<<<N_NODES, 128>>>(gx, ln2_g, ln2_b, gh);
    k_mma_gemm<<<ggemm, 256, SMEM_GEMM>>>(gh, WH(9), WL(9), ffn_b1, nullptr, ga, 1);
    k_mma_gemm<<<ggemm, 256, SMEM_GEMM>>>(ga, WH(10), WL(10), ffn_b2, gx, gh, 0);
    k_gather<<<B_GR * S_SEL, 128>>>(gh, sel, out);
}

// round 6
// speedup vs baseline: 2.0571x; 1.5843x over previous
#include <cuda_runtime.h>
#include <cuda_fp16.h>
#include <cstdint>

// Problem constants (fixed shapes)
constexpr int N_NODES = 8192;
constexpr int D = 512;
constexpr int E_EDGES = 131072;
constexpr int B_GR = 16;
constexpr int NPG = 512;
constexpr int S_SEL = 128;
constexpr int L_LAYERS = 3;

// GEMM tiling
constexpr int BM = 128;
constexpr int BN = 128;
constexpr int BK = 32;             // k-chunk
constexpr int NCH = D / BK;        // 16 chunks
constexpr int NMAT = 11;

// smem stage: padded rows of 80B; A tile + W tile per stage
constexpr int ROWB = 80;
constexpr int SA = 0;              // 128*80 = 10240
constexpr int SW = 10240;
constexpr int STAGE = 20480;
constexpr int SM_IDX = 2 * STAGE;  // edge: sDst (512 B)
constexpr int SMEM_GEMM = 2 * STAGE;
constexpr int SMEM_EDGE = 2 * STAGE + 512;

// -------- static device scratch --------
__device__ float    g_x[N_NODES * D];
__device__ float    g_A[N_NODES * D];
__device__ float    g_B[N_NODES * D];
__device__ unsigned g_agg[N_NODES * D];
__device__ __align__(16) __half g_h16[N_NODES * D];        // LN output (fp16)
__device__ __align__(16) __half g_t16[N_NODES * D];        // FFN intermediate (fp16)
__device__ __align__(16) __half g_y[N_NODES * D];          // (unused pad)
__device__ __align__(16) __half g_Z[(size_t)E_EDGES * D];  // edge features (fp16)
__device__ __align__(16) __half g_W16[(size_t)NMAT * D * D];
__device__ float    g_out[N_NODES * D];                    // final pre-gather output

// ---------------- helpers ----------------
__device__ __forceinline__ unsigned fenc(float f) {
    unsigned b = __float_as_uint(f);
    return (b & 0x80000000u) ? ~b : (b | 0x80000000u);
}
__device__ __forceinline__ float fdec(unsigned u) {
    unsigned b = (u & 0x80000000u) ? (u & 0x7fffffffu) : ~u;
    return __uint_as_float(b);
}
__device__ __forceinline__ uint32_t smem_u32(const void* p) {
    uint32_t a;
    asm("{ .reg .u64 t; cvta.to.shared.u64 t, %1; cvt.u32.u64 %0, t; }" : "=r"(a) : "l"(p));
    return a;
}
__device__ __forceinline__ void cp16(uint32_t dst, const void* src) {
    asm volatile("cp.async.cg.shared.global [%0], [%1], 16;" :: "r"(dst), "l"(src) : "memory");
}
__device__ __forceinline__ void cp_commit() {
    asm volatile("cp.async.commit_group;" ::: "memory");
}
__device__ __forceinline__ void cp_wait0() {
    asm volatile("cp.async.wait_group 0;" ::: "memory");
}
__device__ __forceinline__ void ldm_x4(uint32_t* r, uint32_t addr) {
    asm volatile("ldmatrix.sync.aligned.m8n8.x4.shared.b16 {%0,%1,%2,%3}, [%4];"
                 : "=r"(r[0]), "=r"(r[1]), "=r"(r[2]), "=r"(r[3]) : "r"(addr));
}
__device__ __forceinline__ void mma_h(float* d, const uint32_t* a, uint32_t b0, uint32_t b1) {
    asm volatile(
        "mma.sync.aligned.m16n8k16.row.col.f32.f16.f16.f32 "
        "{%0,%1,%2,%3}, {%4,%5,%6,%7}, {%8,%9}, {%0,%1,%2,%3};"
        : "+f"(d[0]), "+f"(d[1]), "+f"(d[2]), "+f"(d[3])
        : "r"(a[0]), "r"(a[1]), "r"(a[2]), "r"(a[3]), "r"(b0), "r"(b1));
}
// cp.async a 128-row x 32-half chunk into stage offset (2 iters of 256 threads)
__device__ __forceinline__ void cp_rows(uint32_t sbase, const __half* base, int k0, int tid) {
    #pragma unroll
    for (int i = 0; i < 2; i++) {
        int tx = tid + i * 256;
        int row = tx >> 2, seg = tx & 3;
        cp16(sbase + row * ROWB + seg * 16, base + (size_t)row * D + k0 + seg * 8);
    }
}

// ================= init / prep / ln / zbuild / combine / gather =================
__global__ void k_init(const float* __restrict__ x) {
    int i = blockIdx.x * 256 + threadIdx.x;
    g_x[i] = x[i];
    g_agg[i] = 0u;
}

// fp16 weight prep: mats 0..8: l=m/3; r0: Wd=W1top-W1bot; r1: Wb=W1bot; r2: W2^T
// mat 9: ffnW1^T ; 10: ffnW2^T.  Image [n][k] row-major fp16.
__global__ void k_prep16(const float* __restrict__ W1, const float* __restrict__ W2,
                         const float* __restrict__ fW1, const float* __restrict__ fW2,
                         __half* __restrict__ img) {
    int m = blockIdx.y;
    int e = blockIdx.x * 256 + threadIdx.x;
    int n = e & 511, k = e >> 9;
    float w;
    if (m < 9) {
        int l = m / 3, r = m % 3;
        const float* base = W1 + (size_t)l * 2 * D * D;
        if (r == 0)      w = base[(size_t)k * D + n] - base[(size_t)(D + k) * D + n];
        else if (r == 1) w = base[(size_t)(D + k) * D + n];
        else             w = W2[((size_t)l * D + k) * D + n];
    } else if (m == 9)   w = fW1[(size_t)k * D + n];
    else                 w = fW2[(size_t)k * D + n];
    img[(size_t)m * D * D + (size_t)n * D + k] = __float2half(w);
}

// LayerNorm -> fp16 output
__global__ __launch_bounds__(128) void k_ln(const float* __restrict__ x,
                                            const float* __restrict__ gamma,
                                            const float* __restrict__ beta,
                                            __half* __restrict__ out) {
    __shared__ float red[8];
    int row = blockIdx.x;
    int t = threadIdx.x;
    float4 v = ((const float4*)(x + (size_t)row * D))[t];
    float s = v.x + v.y + v.z + v.w;
    #pragma unroll
    for (int o = 16; o > 0; o >>= 1) s += __shfl_xor_sync(0xffffffffu, s, o);
    if ((t & 31) == 0) red[t >> 5] = s;
    __syncthreads();
    if (t == 0) red[4] = red[0] + red[1] + red[2] + red[3];
    __syncthreads();
    float mu = red[4] * (1.0f / D);
    __syncthreads();
    float dx = v.x - mu, dy = v.y - mu, dz = v.z - mu, dw = v.w - mu;
    float q = dx * dx + dy * dy + dz * dz + dw * dw;
    #pragma unroll
    for (int o = 16; o > 0; o >>= 1) q += __shfl_xor_sync(0xffffffffu, q, o);
    if ((t & 31) == 0) red[t >> 5] = q;
    __syncthreads();
    if (t == 0) red[4] = red[0] + red[1] + red[2] + red[3];
    __syncthreads();
    float rstd = rsqrtf(red[4] * (1.0f / D) + 1e-5f);
    float4 g4 = ((const float4*)gamma)[t];
    float4 b4 = ((const float4*)beta)[t];
    __half2 h0 = __floats2half2_rn(dx * rstd * g4.x + b4.x, dy * rstd * g4.y + b4.y);
    __half2 h1 = __floats2half2_rn(dz * rstd * g4.z + b4.z, dw * rstd * g4.w + b4.w);
    *(uint2*)(out + (size_t)row * D + t * 4) =
        make_uint2(*(uint32_t*)&h0, *(uint32_t*)&h1);
}

// Z build: Zh[e][k] = fp16(relu(A[dst[e]][k] + B[src[e]][k])), 4 edges per block
__global__ __launch_bounds__(256) void k_zbuild(const int* __restrict__ src,
                                                const int* __restrict__ dst) {
    int e = blockIdx.x * 4 + (threadIdx.x >> 6);
    int j = (threadIdx.x & 63) * 8;
    int de = dst[e], se = src[e];
    const float4* a = (const float4*)(g_A + (size_t)de * D + j);
    const float4* b = (const float4*)(g_B + (size_t)se * D + j);
    float4 a0 = a[0], a1 = a[1], b0 = b[0], b1 = b[1];
    __half2 p0 = __floats2half2_rn(fmaxf(a0.x + b0.x, 0.f), fmaxf(a0.y + b0.y, 0.f));
    __half2 p1 = __floats2half2_rn(fmaxf(a0.z + b0.z, 0.f), fmaxf(a0.w + b0.w, 0.f));
    __half2 p2 = __floats2half2_rn(fmaxf(a1.x + b1.x, 0.f), fmaxf(a1.y + b1.y, 0.f));
    __half2 p3 = __floats2half2_rn(fmaxf(a1.z + b1.z, 0.f), fmaxf(a1.w + b1.w, 0.f));
    *(uint4*)(g_Z + (size_t)e * D + j) =
        make_uint4(*(uint32_t*)&p0, *(uint32_t*)&p1, *(uint32_t*)&p2, *(uint32_t*)&p3);
}

__global__ void k_combine(const float* __restrict__ b2) {
    int i = blockIdx.x * 256 + threadIdx.x;
    unsigned u = g_agg[i];
    g_agg[i] = 0u;
    float v = (u == 0u) ? 0.0f : (fdec(u) + b2[i & (D - 1)]);
    g_x[i] = fmaxf(v, 0.0f) + g_x[i];
}

__global__ __launch_bounds__(128) void k_gather(const float* __restrict__ y,
                                                const int* __restrict__ sel,
                                                float* __restrict__ out) {
    int r = blockIdx.x;
    int b = r >> 7, s = r & (S_SEL - 1);
    int node = b * NPG + sel[b * S_SEL + s];
    ((float4*)(out + (size_t)r * D))[threadIdx.x] =
        ((const float4*)(y + (size_t)node * D))[threadIdx.x];
}

// ================= dense fp16 GEMM: out = op(A16 @ W + bias [+res]) =================
// grid(x = D/128 = 4, y = M/128), 256 threads, 2 CTAs/SM
__global__ __launch_bounds__(256, 2) void k_mma_gemm(
    const __half* __restrict__ Ain,
    const __half* __restrict__ w,
    const float* __restrict__ bias,
    const float* __restrict__ res,
    float* __restrict__ out,
    __half* __restrict__ out16,
    int relu)
{
    extern __shared__ char smem[];
    int tid = threadIdx.x;
    int n0 = blockIdx.x * BN;
    int m0 = blockIdx.y * BM;

    int lane = tid & 31, wm = (tid >> 5) & 1, wn = tid >> 6;
    const __half* abase = Ain + (size_t)m0 * D;
    const __half* wbase = w + (size_t)n0 * D;

    uint32_t aoff = (uint32_t)(wm * 64 + (lane & 7) + ((lane >> 3) & 1) * 8) * ROWB
                  + ((lane >> 4) & 1) * 16;
    uint32_t boff = (uint32_t)(wn * 32 + (lane & 7) + ((lane >= 16) ? 8 : 0)) * ROWB
                  + ((lane >> 3) & 1) * 16;

    float acc[4][4][4] = {};

    uint32_t s0 = smem_u32(smem), s1 = smem_u32(smem + STAGE);
    cp_rows(s0 + SA, abase, 0, tid);
    cp_rows(s0 + SW, wbase, 0, tid);
    cp_commit();
    cp_wait0();
    __syncthreads();

    for (int c = 0; c < NCH; c++) {
        uint32_t sc = (c & 1) ? s1 : s0;
        uint32_t sn = (c & 1) ? s0 : s1;
        if (c + 1 < NCH) {
            cp_rows(sn + SA, abase, (c + 1) * BK, tid);
            cp_rows(sn + SW, wbase, (c + 1) * BK, tid);
            cp_commit();
        }
        #pragma unroll
        for (int kh = 0; kh < 2; kh++) {
            uint32_t bh[2][4];
            #pragma unroll
            for (int np = 0; np < 2; np++)
                ldm_x4(bh[np], sc + SW + boff + np * 16 * ROWB + kh * 32);
            #pragma unroll
            for (int mf = 0; mf < 4; mf++) {
                uint32_t ah[4];
                ldm_x4(ah, sc + SA + aoff + mf * 16 * ROWB + kh * 32);
                #pragma unroll
                for (int np = 0; np < 2; np++) {
                    #pragma unroll
                    for (int j = 0; j < 2; j++)
                        mma_h(acc[mf][np * 2 + j], ah, bh[np][2 * j], bh[np][2 * j + 1]);
                }
            }
        }
        cp_wait0();
        __syncthreads();
    }

    #pragma unroll
    for (int mf = 0; mf < 4; mf++) {
        int r0 = m0 + wm * 64 + mf * 16 + (lane >> 2);
        int colb = n0 + wn * 32 + 2 * (lane & 3);
        #pragma unroll
        for (int nf = 0; nf < 4; nf++) {
            int col = colb + nf * 8;
            float2 bv = bias ? *(const float2*)(bias + col) : make_float2(0.f, 0.f);
            float c0 = acc[mf][nf][0] + bv.x, c1 = acc[mf][nf][1] + bv.y;
            float c2 = acc[mf][nf][2] + bv.x, c3 = acc[mf][nf][3] + bv.y;
            if (relu) {
                c0 = fmaxf(c0, 0.f); c1 = fmaxf(c1, 0.f);
                c2 = fmaxf(c2, 0.f); c3 = fmaxf(c3, 0.f);
            }
            if (res) {
                float2 r1v = *(const float2*)(res + (size_t)r0 * D + col);
                float2 r2v = *(const float2*)(res + (size_t)(r0 + 8) * D + col);
                c0 += r1v.x; c1 += r1v.y; c2 += r2v.x; c3 += r2v.y;
            }
            if (out) {
                *(float2*)(out + (size_t)r0 * D + col) = make_float2(c0, c1);
                *(float2*)(out + (size_t)(r0 + 8) * D + col) = make_float2(c2, c3);
            }
            if (out16) {
                __half2 h0 = __floats2half2_rn(c0, c1);
                __half2 h1 = __floats2half2_rn(c2, c3);
                *(uint32_t*)(out16 + (size_t)r0 * D + col) = *(uint32_t*)&h0;
                *(uint32_t*)(out16 + (size_t)(r0 + 8) * D + col) = *(uint32_t*)&h1;
            }
        }
    }
}

// ================= edge GEMM: Zh @ W2h -> gated atomicMax =================
// grid(x = D/128 = 4, y = E/128 = 1024), 256 threads, 2 CTAs/SM
__global__ __launch_bounds__(256, 2) void k_mma_edge(
    const __half* __restrict__ w16,
    const int* __restrict__ dst,
    const float* __restrict__ b2,
    unsigned* __restrict__ agg)
{
    extern __shared__ char smem[];
    int tid = threadIdx.x;
    int n0 = blockIdx.x * BN;
    int e0 = blockIdx.y * BM;

    int* sDst = (int*)(smem + SM_IDX);
    if (tid < 128) sDst[tid] = dst[e0 + tid];

    int lane = tid & 31, wm = (tid >> 5) & 1, wn = tid >> 6;
    const __half* abase = g_Z + (size_t)e0 * D;
    const __half* wbase = w16 + (size_t)n0 * D;

    uint32_t aoff = (uint32_t)(wm * 64 + (lane & 7) + ((lane >> 3) & 1) * 8) * ROWB
                  + ((lane >> 4) & 1) * 16;
    uint32_t boff = (uint32_t)(wn * 32 + (lane & 7) + ((lane >= 16) ? 8 : 0)) * ROWB
                  + ((lane >> 3) & 1) * 16;

    float acc[4][4][4] = {};

    uint32_t s0 = smem_u32(smem), s1 = smem_u32(smem + STAGE);
    cp_rows(s0 + SA, abase, 0, tid);
    cp_rows(s0 + SW, wbase, 0, tid);
    cp_commit();
    cp_wait0();
    __syncthreads();

    for (int c = 0; c < NCH; c++) {
        uint32_t sc = (c & 1) ? s1 : s0;
        uint32_t sn = (c & 1) ? s0 : s1;
        if (c + 1 < NCH) {
            cp_rows(sn + SA, abase, (c + 1) * BK, tid);
            cp_rows(sn + SW, wbase, (c + 1) * BK, tid);
            cp_commit();
        }
        #pragma unroll
        for (int kh = 0; kh < 2; kh++) {
            uint32_t bh[2][4];
            #pragma unroll
            for (int np = 0; np < 2; np++)
                ldm_x4(bh[np], sc + SW + boff + np * 16 * ROWB + kh * 32);
            #pragma unroll
            for (int mf = 0; mf < 4; mf++) {
                uint32_t ah[4];
                ldm_x4(ah, sc + SA + aoff + mf * 16 * ROWB + kh * 32);
                #pragma unroll
                for (int np = 0; np < 2; np++) {
                    #pragma unroll
                    for (int j = 0; j < 2; j++)
                        mma_h(acc[mf][np * 2 + j], ah, bh[np][2 * j], bh[np][2 * j + 1]);
                }
            }
        }
        cp_wait0();
        __syncthreads();
    }

    // gated atomic segment-max (v + b2 <= 0 can never affect relu(max+b2))
    #pragma unroll
    for (int mf = 0; mf < 4; mf++) {
        int r0 = wm * 64 + mf * 16 + (lane >> 2);
        int colb = n0 + wn * 32 + 2 * (lane & 3);
        unsigned* p0 = agg + (size_t)sDst[r0] * D + colb;
        unsigned* p1 = agg + (size_t)sDst[r0 + 8] * D + colb;
        #pragma unroll
        for (int nf = 0; nf < 4; nf++) {
            float2 bv = *(const float2*)(b2 + colb + nf * 8);
            float t0 = -bv.x, t1 = -bv.y;
            if (acc[mf][nf][0] > t0) atomicMax(p0 + nf * 8,     fenc(acc[mf][nf][0]));
            if (acc[mf][nf][1] > t1) atomicMax(p0 + nf * 8 + 1, fenc(acc[mf][nf][1]));
            if (acc[mf][nf][2] > t0) atomicMax(p1 + nf * 8,     fenc(acc[mf][nf][2]));
            if (acc[mf][nf][3] > t1) atomicMax(p1 + nf * 8 + 1, fenc(acc[mf][nf][3]));
        }
    }
}

// ================= host launcher =================
extern "C" void kernel_launch(void* const* d_in, const int* in_sizes, int n_in,
                              void* d_out, int out_size) {
    const float* x       = (const float*)d_in[0];
    const int*   eidx    = (const int*)d_in[1];
    const int*   sel     = (const int*)d_in[2];
    const float* conv_W1 = (const float*)d_in[4];
    const float* conv_b1 = (const float*)d_in[5];
    const float* conv_W2 = (const float*)d_in[6];
    const float* conv_b2 = (const float*)d_in[7];
    const float* ln1_g   = (const float*)d_in[8];
    const float* ln1_b   = (const float*)d_in[9];
    const float* ln2_g   = (const float*)d_in[10];
    const float* ln2_b   = (const float*)d_in[11];
    const float* ffn_W1  = (const float*)d_in[12];
    const float* ffn_b1  = (const float*)d_in[13];
    const float* ffn_W2  = (const float*)d_in[14];
    const float* ffn_b2  = (const float*)d_in[15];
    float* out = (float*)d_out;

    const int* src = eidx;
    const int* dst = eidx + E_EDGES;

    float *gx, *ga, *gb, *gout;
    unsigned* gagg;
    __half *gh16, *gt16, *gw16;
    cudaGetSymbolAddress((void**)&gx, g_x);
    cudaGetSymbolAddress((void**)&ga, g_A);
    cudaGetSymbolAddress((void**)&gb, g_B);
    cudaGetSymbolAddress((void**)&gout, g_out);
    cudaGetSymbolAddress((void**)&gagg, g_agg);
    cudaGetSymbolAddress((void**)&gh16, g_h16);
    cudaGetSymbolAddress((void**)&gt16, g_t16);
    cudaGetSymbolAddress((void**)&gw16, g_W16);

    cudaFuncSetAttribute(k_mma_gemm, cudaFuncAttributeMaxDynamicSharedMemorySize, SMEM_GEMM);
    cudaFuncSetAttribute(k_mma_edge, cudaFuncAttributeMaxDynamicSharedMemorySize, SMEM_EDGE);

    auto W = [&](int m) { return gw16 + (size_t)m * D * D; };

    const int ND = N_NODES * D;

    k_init<<<ND / 256, 256>>>(x);
    {
        dim3 grid(1024, NMAT);
        k_prep16<<<grid, 256>>>(conv_W1, conv_W2, ffn_W1, ffn_W2, gw16);
    }

    dim3 ggemm(D / BN, N_NODES / BM);   // (4, 64)
    dim3 gedge(D / BN, E_EDGES / BM);   // (4, 1024)

    for (int l = 0; l < L_LAYERS; l++) {
        k_ln<<<N_NODES, 128>>>(gx, ln1_g, ln1_b, gh16);
        k_mma_gemm<<<ggemm, 256, SMEM_GEMM>>>(gh16, W(l * 3 + 0),
                                              conv_b1 + (size_t)l * D, nullptr,
                                              ga, nullptr, 0);
        k_mma_gemm<<<ggemm, 256, SMEM_GEMM>>>(gh16, W(l * 3 + 1),
                                              nullptr, nullptr, gb, nullptr, 0);
        k_zbuild<<<E_EDGES / 4, 256>>>(src, dst);
        k_mma_edge<<<gedge, 256, SMEM_EDGE>>>(W(l * 3 + 2), dst,
                                              conv_b2 + (size_t)l * D, gagg);
        k_combine<<<ND / 256, 256>>>(conv_b2 + (size_t)l * D);
    }

    k_ln<<<N_NODES, 128>>>(gx, ln2_g, ln2_b, gh16);
    k_mma_gemm<<<ggemm, 256, SMEM_GEMM>>>(gh16, W(9), ffn_b1, nullptr,
                                          nullptr, gt16, 1);
    k_mma_gemm<<<ggemm, 256, SMEM_GEMM>>>(gt16, W(10), ffn_b2, gx,
                                          gout, nullptr, 0);
    k_gather<<<B_GR * S_SEL, 128>>>(gout, sel, out);
}

// round 7
// speedup vs baseline: 2.5228x; 1.2264x over previous
#include <cuda_runtime.h>
#include <cuda_fp16.h>
#include <cstdint>

// Problem constants (fixed shapes)
constexpr int N_NODES = 8192;
constexpr int D = 512;
constexpr int E_EDGES = 131072;
constexpr int B_GR = 16;
constexpr int NPG = 512;
constexpr int S_SEL = 128;
constexpr int L_LAYERS = 3;

// GEMM tiling
constexpr int BM = 128;
constexpr int BN = 128;
constexpr int BK = 64;             // k-chunk (64 halfs = 128 B/row)
constexpr int NCH = D / BK;        // 8 chunks
constexpr int NMAT = 11;

// smem stage: padded rows of 144B (64 halfs + 16B pad); A tile + W tile per stage
constexpr int ROWB = 144;
constexpr int SA = 0;              // 128*144 = 18432
constexpr int SW = 18432;
constexpr int STAGE = 36864;
constexpr int NSTG = 3;
constexpr int SM_IDX = NSTG * STAGE;   // edge: sDst (512 B)
constexpr int SMEM_GEMM = NSTG * STAGE;          // 110592
constexpr int SMEM_EDGE = NSTG * STAGE + 512;    // 111104

// -------- static device scratch --------
__device__ float    g_x[N_NODES * D];
__device__ float    g_A[N_NODES * D];
__device__ float    g_B[N_NODES * D];
__device__ unsigned g_agg[N_NODES * D];
__device__ __align__(16) __half g_h16[N_NODES * D];        // LN output (fp16)
__device__ __align__(16) __half g_t16[N_NODES * D];        // FFN intermediate (fp16)
__device__ __align__(16) __half g_Z[(size_t)E_EDGES * D];  // edge features (fp16)
__device__ __align__(16) __half g_W16[(size_t)NMAT * D * D];
__device__ float    g_out[N_NODES * D];                    // final pre-gather output

// ---------------- helpers ----------------
__device__ __forceinline__ unsigned fenc(float f) {
    unsigned b = __float_as_uint(f);
    return (b & 0x80000000u) ? ~b : (b | 0x80000000u);
}
__device__ __forceinline__ float fdec(unsigned u) {
    unsigned b = (u & 0x80000000u) ? (u & 0x7fffffffu) : ~u;
    return __uint_as_float(b);
}
__device__ __forceinline__ uint32_t smem_u32(const void* p) {
    uint32_t a;
    asm("{ .reg .u64 t; cvta.to.shared.u64 t, %1; cvt.u32.u64 %0, t; }" : "=r"(a) : "l"(p));
    return a;
}
__device__ __forceinline__ void cp16(uint32_t dst, const void* src) {
    asm volatile("cp.async.cg.shared.global [%0], [%1], 16;" :: "r"(dst), "l"(src) : "memory");
}
__device__ __forceinline__ void cp_commit() {
    asm volatile("cp.async.commit_group;" ::: "memory");
}
template <int N>
__device__ __forceinline__ void cp_wait() {
    asm volatile("cp.async.wait_group %0;" :: "n"(N) : "memory");
}
__device__ __forceinline__ void ldm_x4(uint32_t* r, uint32_t addr) {
    asm volatile("ldmatrix.sync.aligned.m8n8.x4.shared.b16 {%0,%1,%2,%3}, [%4];"
                 : "=r"(r[0]), "=r"(r[1]), "=r"(r[2]), "=r"(r[3]) : "r"(addr));
}
__device__ __forceinline__ void mma_h(float* d, const uint32_t* a, uint32_t b0, uint32_t b1) {
    asm volatile(
        "mma.sync.aligned.m16n8k16.row.col.f32.f16.f16.f32 "
        "{%0,%1,%2,%3}, {%4,%5,%6,%7}, {%8,%9}, {%0,%1,%2,%3};"
        : "+f"(d[0]), "+f"(d[1]), "+f"(d[2]), "+f"(d[3])
        : "r"(a[0]), "r"(a[1]), "r"(a[2]), "r"(a[3]), "r"(b0), "r"(b1));
}
// cp.async a 128-row x 64-half chunk into stage offset (4 iters of 256 threads)
__device__ __forceinline__ void cp_rows(uint32_t sbase, const __half* base, int k0, int tid) {
    #pragma unroll
    for (int i = 0; i < 4; i++) {
        int tx = tid + i * 256;            // 0..1023
        int row = tx >> 3, seg = tx & 7;
        cp16(sbase + row * ROWB + seg * 16, base + (size_t)row * D + k0 + seg * 8);
    }
}

// ================= init / prep / lnc / zbuild / gather =================
__global__ void k_init(const float* __restrict__ x) {
    int i = blockIdx.x * 256 + threadIdx.x;
    g_x[i] = x[i];
    g_agg[i] = 0u;
}

// fp16 weight prep: mats 0..8: l=m/3; r0: Wd=W1top-W1bot; r1: Wb=W1bot; r2: W2^T
// mat 9: ffnW1^T ; 10: ffnW2^T.  Image [n][k] row-major fp16.
__global__ void k_prep16(const float* __restrict__ W1, const float* __restrict__ W2,
                         const float* __restrict__ fW1, const float* __restrict__ fW2,
                         __half* __restrict__ img) {
    int m = blockIdx.y;
    int e = blockIdx.x * 256 + threadIdx.x;
    int n = e & 511, k = e >> 9;
    float w;
    if (m < 9) {
        int l = m / 3, r = m % 3;
        const float* base = W1 + (size_t)l * 2 * D * D;
        if (r == 0)      w = base[(size_t)k * D + n] - base[(size_t)(D + k) * D + n];
        else if (r == 1) w = base[(size_t)(D + k) * D + n];
        else             w = W2[((size_t)l * D + k) * D + n];
    } else if (m == 9)   w = fW1[(size_t)k * D + n];
    else                 w = fW2[(size_t)k * D + n];
    img[(size_t)m * D * D + (size_t)n * D + k] = __float2half(w);
}

// fused combine (optional) + LayerNorm -> fp16.
// useAgg: x' = relu(dec(agg)+b2) + x (agg reset to 0, x' written back); then LN(x') -> out
__global__ __launch_bounds__(128) void k_lnc(int useAgg,
                                             const float* __restrict__ b2,
                                             const float* __restrict__ gamma,
                                             const float* __restrict__ beta,
                                             __half* __restrict__ out) {
    __shared__ float red[8];
    int row = blockIdx.x;
    int t = threadIdx.x;
    size_t base = (size_t)row * D + t * 4;
    float4 v = *(const float4*)(g_x + base);
    if (useAgg) {
        uint4 u = *(const uint4*)(g_agg + base);
        *(uint4*)(g_agg + base) = make_uint4(0u, 0u, 0u, 0u);
        float4 bv = ((const float4*)b2)[t];
        float m0 = u.x ? fdec(u.x) + bv.x : 0.f;
        float m1 = u.y ? fdec(u.y) + bv.y : 0.f;
        float m2 = u.z ? fdec(u.z) + bv.z : 0.f;
        float m3 = u.w ? fdec(u.w) + bv.w : 0.f;
        v.x += fmaxf(m0, 0.f); v.y += fmaxf(m1, 0.f);
        v.z += fmaxf(m2, 0.f); v.w += fmaxf(m3, 0.f);
        *(float4*)(g_x + base) = v;
    }
    float s = v.x + v.y + v.z + v.w;
    #pragma unroll
    for (int o = 16; o > 0; o >>= 1) s += __shfl_xor_sync(0xffffffffu, s, o);
    if ((t & 31) == 0) red[t >> 5] = s;
    __syncthreads();
    if (t == 0) red[4] = red[0] + red[1] + red[2] + red[3];
    __syncthreads();
    float mu = red[4] * (1.0f / D);
    __syncthreads();
    float dx = v.x - mu, dy = v.y - mu, dz = v.z - mu, dw = v.w - mu;
    float q = dx * dx + dy * dy + dz * dz + dw * dw;
    #pragma unroll
    for (int o = 16; o > 0; o >>= 1) q += __shfl_xor_sync(0xffffffffu, q, o);
    if ((t & 31) == 0) red[t >> 5] = q;
    __syncthreads();
    if (t == 0) red[4] = red[0] + red[1] + red[2] + red[3];
    __syncthreads();
    float rstd = rsqrtf(red[4] * (1.0f / D) + 1e-5f);
    float4 g4 = ((const float4*)gamma)[t];
    float4 b4 = ((const float4*)beta)[t];
    __half2 h0 = __floats2half2_rn(dx * rstd * g4.x + b4.x, dy * rstd * g4.y + b4.y);
    __half2 h1 = __floats2half2_rn(dz * rstd * g4.z + b4.z, dw * rstd * g4.w + b4.w);
    *(uint2*)(out + base) = make_uint2(*(uint32_t*)&h0, *(uint32_t*)&h1);
}

// Z build: Zh[e][k] = fp16(relu(A[dst[e]][k] + B[src[e]][k])), 4 edges per block
__global__ __launch_bounds__(256) void k_zbuild(const int* __restrict__ src,
                                                const int* __restrict__ dst) {
    int e = blockIdx.x * 4 + (threadIdx.x >> 6);
    int j = (threadIdx.x & 63) * 8;
    int de = dst[e], se = src[e];
    const float4* a = (const float4*)(g_A + (size_t)de * D + j);
    const float4* b = (const float4*)(g_B + (size_t)se * D + j);
    float4 a0 = a[0], a1 = a[1], b0 = b[0], b1 = b[1];
    __half2 p0 = __floats2half2_rn(fmaxf(a0.x + b0.x, 0.f), fmaxf(a0.y + b0.y, 0.f));
    __half2 p1 = __floats2half2_rn(fmaxf(a0.z + b0.z, 0.f), fmaxf(a0.w + b0.w, 0.f));
    __half2 p2 = __floats2half2_rn(fmaxf(a1.x + b1.x, 0.f), fmaxf(a1.y + b1.y, 0.f));
    __half2 p3 = __floats2half2_rn(fmaxf(a1.z + b1.z, 0.f), fmaxf(a1.w + b1.w, 0.f));
    *(uint4*)(g_Z + (size_t)e * D + j) =
        make_uint4(*(uint32_t*)&p0, *(uint32_t*)&p1, *(uint32_t*)&p2, *(uint32_t*)&p3);
}

__global__ __launch_bounds__(128) void k_gather(const float* __restrict__ y,
                                                const int* __restrict__ sel,
                                                float* __restrict__ out) {
    int r = blockIdx.x;
    int b = r >> 7, s = r & (S_SEL - 1);
    int node = b * NPG + sel[b * S_SEL + s];
    ((float4*)(out + (size_t)r * D))[threadIdx.x] =
        ((const float4*)(y + (size_t)node * D))[threadIdx.x];
}

// ---------------- shared GEMM mainloop (macro-ish inline) ----------------
struct GemmCtx {
    uint32_t s[NSTG];
    const __half* abase;
    const __half* wbase;
    int tid;
    uint32_t aoff, boff;
};

__device__ __forceinline__ void gemm_mainloop(GemmCtx& g, float acc[4][4][4]) {
    // prologue: chunks 0,1 into stages 0,1
    cp_rows(g.s[0] + SA, g.abase, 0, g.tid);
    cp_rows(g.s[0] + SW, g.wbase, 0, g.tid);
    cp_commit();
    cp_rows(g.s[1] + SA, g.abase, BK, g.tid);
    cp_rows(g.s[1] + SW, g.wbase, BK, g.tid);
    cp_commit();
    cp_wait<1>();           // chunk 0 ready
    __syncthreads();

    for (int c = 0; c < NCH; c++) {
        uint32_t sc = g.s[c % NSTG];
        if (c + 2 < NCH) {
            uint32_t sn = g.s[(c + 2) % NSTG];
            cp_rows(sn + SA, g.abase, (c + 2) * BK, g.tid);
            cp_rows(sn + SW, g.wbase, (c + 2) * BK, g.tid);
            cp_commit();
        }
        #pragma unroll
        for (int kh = 0; kh < 4; kh++) {
            uint32_t bh[2][4];
            #pragma unroll
            for (int np = 0; np < 2; np++)
                ldm_x4(bh[np], sc + SW + g.boff + np * 16 * ROWB + kh * 32);
            #pragma unroll
            for (int mf = 0; mf < 4; mf++) {
                uint32_t ah[4];
                ldm_x4(ah, sc + SA + g.aoff + mf * 16 * ROWB + kh * 32);
                #pragma unroll
                for (int np = 0; np < 2; np++) {
                    #pragma unroll
                    for (int j = 0; j < 2; j++)
                        mma_h(acc[mf][np * 2 + j], ah, bh[np][2 * j], bh[np][2 * j + 1]);
                }
            }
        }
        if (c + 2 < NCH) cp_wait<1>();          // chunk c+1 done, c+2 may pend
        else if (c + 1 < NCH) cp_wait<0>();     // drain: chunk c+1 done
        __syncthreads();
    }
}

// ================= dense fp16 GEMM: out = op(A16 @ W + bias [+res]) =================
// grid(x = D/128 = 4, y = M/128), 256 threads, 2 CTAs/SM
__global__ __launch_bounds__(256, 2) void k_mma_gemm(
    const __half* __restrict__ Ain,
    const __half* __restrict__ w,
    const float* __restrict__ bias,
    const float* __restrict__ res,
    float* __restrict__ out,
    __half* __restrict__ out16,
    int relu)
{
    extern __shared__ char smem[];
    int tid = threadIdx.x;
    int n0 = blockIdx.x * BN;
    int m0 = blockIdx.y * BM;
    int lane = tid & 31, wm = (tid >> 5) & 1, wn = tid >> 6;

    GemmCtx g;
    #pragma unroll
    for (int i = 0; i < NSTG; i++) g.s[i] = smem_u32(smem + i * STAGE);
    g.abase = Ain + (size_t)m0 * D;
    g.wbase = w + (size_t)n0 * D;
    g.tid = tid;
    g.aoff = (uint32_t)(wm * 64 + (lane & 7) + ((lane >> 3) & 1) * 8) * ROWB
           + ((lane >> 4) & 1) * 16;
    g.boff = (uint32_t)(wn * 32 + (lane & 7) + ((lane >= 16) ? 8 : 0)) * ROWB
           + ((lane >> 3) & 1) * 16;

    float acc[4][4][4] = {};
    gemm_mainloop(g, acc);

    #pragma unroll
    for (int mf = 0; mf < 4; mf++) {
        int r0 = m0 + wm * 64 + mf * 16 + (lane >> 2);
        int colb = n0 + wn * 32 + 2 * (lane & 3);
        #pragma unroll
        for (int nf = 0; nf < 4; nf++) {
            int col = colb + nf * 8;
            float2 bv = bias ? *(const float2*)(bias + col) : make_float2(0.f, 0.f);
            float c0 = acc[mf][nf][0] + bv.x, c1 = acc[mf][nf][1] + bv.y;
            float c2 = acc[mf][nf][2] + bv.x, c3 = acc[mf][nf][3] + bv.y;
            if (relu) {
                c0 = fmaxf(c0, 0.f); c1 = fmaxf(c1, 0.f);
                c2 = fmaxf(c2, 0.f); c3 = fmaxf(c3, 0.f);
            }
            if (res) {
                float2 r1v = *(const float2*)(res + (size_t)r0 * D + col);
                float2 r2v = *(const float2*)(res + (size_t)(r0 + 8) * D + col);
                c0 += r1v.x; c1 += r1v.y; c2 += r2v.x; c3 += r2v.y;
            }
            if (out) {
                *(float2*)(out + (size_t)r0 * D + col) = make_float2(c0, c1);
                *(float2*)(out + (size_t)(r0 + 8) * D + col) = make_float2(c2, c3);
            }
            if (out16) {
                __half2 h0 = __floats2half2_rn(c0, c1);
                __half2 h1 = __floats2half2_rn(c2, c3);
                *(uint32_t*)(out16 + (size_t)r0 * D + col) = *(uint32_t*)&h0;
                *(uint32_t*)(out16 + (size_t)(r0 + 8) * D + col) = *(uint32_t*)&h1;
            }
        }
    }
}

// ================= edge GEMM: Zh @ W2h -> gated atomicMax =================
// grid(x = D/128 = 4, y = E/128 = 1024), 256 threads, 2 CTAs/SM
__global__ __launch_bounds__(256, 2) void k_mma_edge(
    const __half* __restrict__ w16,
    const int* __restrict__ dst,
    const float* __restrict__ b2,
    unsigned* __restrict__ agg)
{
    extern __shared__ char smem[];
    int tid = threadIdx.x;
    int n0 = blockIdx.x * BN;
    int e0 = blockIdx.y * BM;
    int lane = tid & 31, wm = (tid >> 5) & 1, wn = tid >> 6;

    int* sDst = (int*)(smem + SM_IDX);
    if (tid < 128) sDst[tid] = dst[e0 + tid];

    GemmCtx g;
    #pragma unroll
    for (int i = 0; i < NSTG; i++) g.s[i] = smem_u32(smem + i * STAGE);
    g.abase = g_Z + (size_t)e0 * D;
    g.wbase = w16 + (size_t)n0 * D;
    g.tid = tid;
    g.aoff = (uint32_t)(wm * 64 + (lane & 7) + ((lane >> 3) & 1) * 8) * ROWB
           + ((lane >> 4) & 1) * 16;
    g.boff = (uint32_t)(wn * 32 + (lane & 7) + ((lane >= 16) ? 8 : 0)) * ROWB
           + ((lane >> 3) & 1) * 16;

    float acc[4][4][4] = {};
    gemm_mainloop(g, acc);

    // gated atomic segment-max (v + b2 <= 0 can never affect relu(max+b2))
    #pragma unroll
    for (int mf = 0; mf < 4; mf++) {
        int r0 = wm * 64 + mf * 16 + (lane >> 2);
        int colb = n0 + wn * 32 + 2 * (lane & 3);
        unsigned* p0 = agg + (size_t)sDst[r0] * D + colb;
        unsigned* p1 = agg + (size_t)sDst[r0 + 8] * D + colb;
        #pragma unroll
        for (int nf = 0; nf < 4; nf++) {
            float2 bv = *(const float2*)(b2 + colb + nf * 8);
            float t0 = -bv.x, t1 = -bv.y;
            if (acc[mf][nf][0] > t0) atomicMax(p0 + nf * 8,     fenc(acc[mf][nf][0]));
            if (acc[mf][nf][1] > t1) atomicMax(p0 + nf * 8 + 1, fenc(acc[mf][nf][1]));
            if (acc[mf][nf][2] > t0) atomicMax(p1 + nf * 8,     fenc(acc[mf][nf][2]));
            if (acc[mf][nf][3] > t1) atomicMax(p1 + nf * 8 + 1, fenc(acc[mf][nf][3]));
        }
    }
}

// ================= host launcher =================
extern "C" void kernel_launch(void* const* d_in, const int* in_sizes, int n_in,
                              void* d_out, int out_size) {
    const float* x       = (const float*)d_in[0];
    const int*   eidx    = (const int*)d_in[1];
    const int*   sel     = (const int*)d_in[2];
    const float* conv_W1 = (const float*)d_in[4];
    const float* conv_b1 = (const float*)d_in[5];
    const float* conv_W2 = (const float*)d_in[6];
    const float* conv_b2 = (const float*)d_in[7];
    const float* ln1_g   = (const float*)d_in[8];
    const float* ln1_b   = (const float*)d_in[9];
    const float* ln2_g   = (const float*)d_in[10];
    const float* ln2_b   = (const float*)d_in[11];
    const float* ffn_W1  = (const float*)d_in[12];
    const float* ffn_b1  = (const float*)d_in[13];
    const float* ffn_W2  = (const float*)d_in[14];
    const float* ffn_b2  = (const float*)d_in[15];
    float* out = (float*)d_out;

    const int* src = eidx;
    const int* dst = eidx + E_EDGES;

    float *gx, *ga, *gb, *gout;
    unsigned* gagg;
    __half *gh16, *gt16, *gw16;
    cudaGetSymbolAddress((void**)&gx, g_x);
    cudaGetSymbolAddress((void**)&ga, g_A);
    cudaGetSymbolAddress((void**)&gb, g_B);
    cudaGetSymbolAddress((void**)&gout, g_out);
    cudaGetSymbolAddress((void**)&gagg, g_agg);
    cudaGetSymbolAddress((void**)&gh16, g_h16);
    cudaGetSymbolAddress((void**)&gt16, g_t16);
    cudaGetSymbolAddress((void**)&gw16, g_W16);

    cudaFuncSetAttribute(k_mma_gemm, cudaFuncAttributeMaxDynamicSharedMemorySize, SMEM_GEMM);
    cudaFuncSetAttribute(k_mma_edge, cudaFuncAttributeMaxDynamicSharedMemorySize, SMEM_EDGE);

    auto W = [&](int m) { return gw16 + (size_t)m * D * D; };

    const int ND = N_NODES * D;

    k_init<<<ND / 256, 256>>>(x);
    {
        dim3 grid(1024, NMAT);
        k_prep16<<<grid, 256>>>(conv_W1, conv_W2, ffn_W1, ffn_W2, gw16);
    }

    dim3 ggemm(D / BN, N_NODES / BM);   // (4, 64)
    dim3 gedge(D / BN, E_EDGES / BM);   // (4, 1024)

    for (int l = 0; l < L_LAYERS; l++) {
        // combine previous layer's agg (if any) + LN -> h16
        if (l == 0)
            k_lnc<<<N_NODES, 128>>>(0, conv_b2, ln1_g, ln1_b, gh16);
        else
            k_lnc<<<N_NODES, 128>>>(1, conv_b2 + (size_t)(l - 1) * D, ln1_g, ln1_b, gh16);
        k_mma_gemm<<<ggemm, 256, SMEM_GEMM>>>(gh16, W(l * 3 + 0),
                                              conv_b1 + (size_t)l * D, nullptr,
                                              ga, nullptr, 0);
        k_mma_gemm<<<ggemm, 256, SMEM_GEMM>>>(gh16, W(l * 3 + 1),
                                              nullptr, nullptr, gb, nullptr, 0);
        k_zbuild<<<E_EDGES / 4, 256>>>(src, dst);
        k_mma_edge<<<gedge, 256, SMEM_EDGE>>>(W(l * 3 + 2), dst,
                                              conv_b2 + (size_t)l * D, gagg);
    }

    // final: combine layer-2 agg + LN2 -> h16, then FFN + residual, gather
    k_lnc<<<N_NODES, 128>>>(1, conv_b2 + (size_t)2 * D, ln2_g, ln2_b, gh16);
    k_mma_gemm<<<ggemm, 256, SMEM_GEMM>>>(gh16, W(9), ffn_b1, nullptr,
                                          nullptr, gt16, 1);
    k_mma_gemm<<<ggemm, 256, SMEM_GEMM>>>(gt16, W(10), ffn_b2, gx,
                                          gout, nullptr, 0);
    k_gather<<<B_GR * S_SEL, 128>>>(gout, sel, out);
}